// round 1
// baseline (speedup 1.0000x reference)
#include <cuda_runtime.h>
#include <cuda_bf16.h>
#include <cstdint>

// ---------------- problem constants ----------------
#define S_LEN  2048
#define HIDDEN 2048
#define NHEADS 16
#define HD     128
#define LATENT 512
#define BATCH  2
#define ROWS   (BATCH * S_LEN)        // 4096
#define ATT_SCALE 0.088388347648318447f   // 128^-0.5

// ---------------- scratch (static device globals; no allocation) ------------
static __device__ float g_Wq_eff[(size_t)HIDDEN * HIDDEN];   // 16 MB
static __device__ float g_Wk_eff[(size_t)LATENT * HIDDEN];   //  4 MB
static __device__ float g_q  [(size_t)ROWS * HIDDEN];        // 32 MB
static __device__ float g_kv [(size_t)ROWS * (2 * LATENT)];  // 16 MB
static __device__ float g_k  [(size_t)ROWS * HIDDEN];        // 32 MB
static __device__ float g_v  [(size_t)ROWS * HIDDEN];        // 32 MB
static __device__ float g_ao [(size_t)ROWS * HIDDEN];        // 32 MB

// ---------------- elementwise weight fold ----------------
__global__ void add2_kernel(const float* __restrict__ a,
                            const float* __restrict__ b,
                            float* __restrict__ c, int n) {
    int i = blockIdx.x * blockDim.x + threadIdx.x;
    if (i < n) c[i] = a[i] + b[i];
}

// ---------------- fp32 SGEMM: C[M,N] = A[M,K] @ B[K,N] ----------------
// 128x128 block tile, BK=8, 256 threads, 8x8 per-thread microtile.
// All M,N,K used here are multiples of tile dims -> no bounds checks.
#define BM 128
#define BN 128
#define BK 8

__global__ __launch_bounds__(256)
void sgemm_kernel(int M, int N, int K,
                  const float* __restrict__ A, int lda,
                  const float* __restrict__ B, int ldb,
                  float* __restrict__ C, int ldc)
{
    __shared__ float As[BK][BM];        // transposed A tile
    __shared__ float Bs[BK][BN + 4];    // pad keeps 16B row alignment (132 floats)

    const int tid = threadIdx.x;
    const int bm = blockIdx.y * BM;
    const int bn = blockIdx.x * BN;
    const int tr = tid >> 4;            // 0..15
    const int tc = tid & 15;            // 0..15

    // A loader: thread -> one float4 (row = tid/2, kcol = (tid&1)*4)
    const int a_row = tid >> 1;
    const int a_col = (tid & 1) << 2;
    // B loader: thread -> one float4 (krow = tid/32, ncol = (tid%32)*4)
    const int b_row = tid >> 5;
    const int b_col = (tid & 31) << 2;

    const float* Aptr = A + (size_t)bm * lda;
    const float* Bptr = B + bn;

    float acc[8][8];
#pragma unroll
    for (int i = 0; i < 8; i++)
#pragma unroll
        for (int j = 0; j < 8; j++) acc[i][j] = 0.f;

    for (int k0 = 0; k0 < K; k0 += BK) {
        float4 av = *(const float4*)(Aptr + (size_t)a_row * lda + k0 + a_col);
        As[a_col + 0][a_row] = av.x;
        As[a_col + 1][a_row] = av.y;
        As[a_col + 2][a_row] = av.z;
        As[a_col + 3][a_row] = av.w;
        float4 bv = *(const float4*)(Bptr + (size_t)(k0 + b_row) * ldb + b_col);
        *(float4*)&Bs[b_row][b_col] = bv;
        __syncthreads();

#pragma unroll
        for (int kk = 0; kk < BK; kk++) {
            float af[8], bf[8];
            *(float4*)&af[0] = *(const float4*)&As[kk][tr * 8];
            *(float4*)&af[4] = *(const float4*)&As[kk][tr * 8 + 4];
            *(float4*)&bf[0] = *(const float4*)&Bs[kk][tc * 8];
            *(float4*)&bf[4] = *(const float4*)&Bs[kk][tc * 8 + 4];
#pragma unroll
            for (int i = 0; i < 8; i++)
#pragma unroll
                for (int j = 0; j < 8; j++)
                    acc[i][j] += af[i] * bf[j];
        }
        __syncthreads();
    }

#pragma unroll
    for (int i = 0; i < 8; i++) {
        float* crow = C + (size_t)(bm + tr * 8 + i) * ldc + bn + tc * 8;
        float4 v0 = make_float4(acc[i][0], acc[i][1], acc[i][2], acc[i][3]);
        float4 v1 = make_float4(acc[i][4], acc[i][5], acc[i][6], acc[i][7]);
        *(float4*)(crow)     = v0;
        *(float4*)(crow + 4) = v1;
    }
}

// ---------------- causal flash attention (fp32) ----------------
// Br = Bc = 64, D = 128. Block: 256 threads (ty = tid/16, tx = tid%16).
// Thread owns S rows [ty*4, ty*4+4), S cols [tx*4, tx*4+4),
//             O rows [ty*4, ty*4+4), O cols [tx*8, tx*8+8).
// Q,K stored d-major in smem: [128][64]; V as [64][132]; P as [64][68].
#define AT_BR 64
#define AT_BC 64
#define VS_LD 132
#define PS_LD 68

__global__ __launch_bounds__(256)
void flash_attn_kernel(const float* __restrict__ Qg,
                       const float* __restrict__ Kg,
                       const float* __restrict__ Vg,
                       float* __restrict__ Og)
{
    extern __shared__ float sm[];
    float* Qs = sm;                    // 128*64
    float* Ks = Qs + 128 * 64;         // 128*64
    float* Vs = Ks + 128 * 64;         // 64*132
    float* Ps = Vs + 64 * VS_LD;       // 64*68

    const int qt = blockIdx.x;                 // query tile 0..31
    const int bh = blockIdx.y;                 // 0..31
    const int b  = bh >> 4;
    const int h  = bh & 15;
    const int tid = threadIdx.x;
    const int ty = tid >> 4;
    const int tx = tid & 15;

    const size_t ldq = HIDDEN;
    const float* qbase = Qg + (size_t)(b * S_LEN + qt * AT_BR) * ldq + h * HD;

    // load Q tile transposed + pre-scaled
#pragma unroll
    for (int it = 0; it < 32; it++) {
        int idx = tid + it * 256;
        int r = idx >> 7, d = idx & 127;
        Qs[d * 64 + r] = qbase[(size_t)r * ldq + d] * ATT_SCALE;
    }

    float acc[4][8];
#pragma unroll
    for (int i = 0; i < 4; i++)
#pragma unroll
        for (int j = 0; j < 8; j++) acc[i][j] = 0.f;
    float m_i[4] = {-1e30f, -1e30f, -1e30f, -1e30f};
    float l_i[4] = {0.f, 0.f, 0.f, 0.f};

    for (int kt = 0; kt <= qt; kt++) {
        const float* kbase = Kg + (size_t)(b * S_LEN + kt * AT_BC) * ldq + h * HD;
        const float* vbase = Vg + (size_t)(b * S_LEN + kt * AT_BC) * ldq + h * HD;
#pragma unroll
        for (int it = 0; it < 32; it++) {
            int idx = tid + it * 256;
            int r = idx >> 7, d = idx & 127;
            Ks[d * 64 + r]    = kbase[(size_t)r * ldq + d];
            Vs[r * VS_LD + d] = vbase[(size_t)r * ldq + d];
        }
        __syncthreads();

        // S = (Q*scale) @ K^T : 4x4 per thread
        float s[4][4];
#pragma unroll
        for (int i = 0; i < 4; i++)
#pragma unroll
            for (int j = 0; j < 4; j++) s[i][j] = 0.f;

#pragma unroll 8
        for (int d = 0; d < 128; d++) {
            float4 qf = *(const float4*)&Qs[d * 64 + ty * 4];
            float4 kf = *(const float4*)&Ks[d * 64 + tx * 4];
            float qa[4] = {qf.x, qf.y, qf.z, qf.w};
            float ka[4] = {kf.x, kf.y, kf.z, kf.w};
#pragma unroll
            for (int i = 0; i < 4; i++)
#pragma unroll
                for (int j = 0; j < 4; j++)
                    s[i][j] += qa[i] * ka[j];
        }

        // causal mask on diagonal tile (additive -1e9, matching reference)
        if (kt == qt) {
#pragma unroll
            for (int i = 0; i < 4; i++)
#pragma unroll
                for (int j = 0; j < 4; j++)
                    if (tx * 4 + j > ty * 4 + i) s[i][j] -= 1e9f;
        }

        // online softmax (per-row reduce across the 16 tx lanes via shuffle)
#pragma unroll
        for (int i = 0; i < 4; i++) {
            float mt = fmaxf(fmaxf(s[i][0], s[i][1]), fmaxf(s[i][2], s[i][3]));
#pragma unroll
            for (int off = 8; off > 0; off >>= 1)
                mt = fmaxf(mt, __shfl_xor_sync(0xffffffffu, mt, off));
            float mnew = fmaxf(m_i[i], mt);
            float corr = __expf(m_i[i] - mnew);
            float p[4], rs = 0.f;
#pragma unroll
            for (int j = 0; j < 4; j++) { p[j] = __expf(s[i][j] - mnew); rs += p[j]; }
#pragma unroll
            for (int off = 8; off > 0; off >>= 1)
                rs += __shfl_xor_sync(0xffffffffu, rs, off);
            l_i[i] = l_i[i] * corr + rs;
            m_i[i] = mnew;
#pragma unroll
            for (int j = 0; j < 8; j++) acc[i][j] *= corr;
#pragma unroll
            for (int j = 0; j < 4; j++)
                Ps[(ty * 4 + i) * PS_LD + tx * 4 + j] = p[j];
        }
        __syncthreads();

        // O += P @ V
#pragma unroll 4
        for (int kk = 0; kk < AT_BC; kk++) {
            float vf[8];
            *(float4*)&vf[0] = *(const float4*)&Vs[kk * VS_LD + tx * 8];
            *(float4*)&vf[4] = *(const float4*)&Vs[kk * VS_LD + tx * 8 + 4];
            float pr[4];
#pragma unroll
            for (int i = 0; i < 4; i++) pr[i] = Ps[(ty * 4 + i) * PS_LD + kk];
#pragma unroll
            for (int i = 0; i < 4; i++)
#pragma unroll
                for (int j = 0; j < 8; j++)
                    acc[i][j] += pr[i] * vf[j];
        }
        __syncthreads();
    }

    // normalize + write
#pragma unroll
    for (int i = 0; i < 4; i++) {
        float inv = 1.f / l_i[i];
        size_t gr = (size_t)(b * S_LEN + qt * AT_BR + ty * 4 + i);
        float* orow = Og + gr * ldq + h * HD + tx * 8;
        float4 v0 = make_float4(acc[i][0] * inv, acc[i][1] * inv,
                                acc[i][2] * inv, acc[i][3] * inv);
        float4 v1 = make_float4(acc[i][4] * inv, acc[i][5] * inv,
                                acc[i][6] * inv, acc[i][7] * inv);
        *(float4*)(orow)     = v0;
        *(float4*)(orow + 4) = v1;
    }
}

// ---------------- launch ----------------
extern "C" void kernel_launch(void* const* d_in, const int* in_sizes, int n_in,
                              void* d_out, int out_size)
{
    const float* h       = (const float*)d_in[0];  // (2,2048,2048)
    // d_in[1] attention_mask: pure causal, folded into kernel
    // d_in[2] position_ids:   unused by the math
    const float* Wq      = (const float*)d_in[3];  // (2048,2048)
    const float* Wkv     = (const float*)d_in[4];  // (2048,1024)
    const float* Wk_up   = (const float*)d_in[5];  // (512,2048)
    const float* Wv_up   = (const float*)d_in[6];  // (512,2048)
    const float* Wq_rope = (const float*)d_in[7];  // (2048,2048)
    const float* Wk_rope = (const float*)d_in[8];  // (512,2048)
    const float* Wo      = (const float*)d_in[9];  // (2048,2048)
    float* out = (float*)d_out;

    float *pWq_eff, *pWk_eff, *pq, *pkv, *pk, *pv, *pao;
    cudaGetSymbolAddress((void**)&pWq_eff, g_Wq_eff);
    cudaGetSymbolAddress((void**)&pWk_eff, g_Wk_eff);
    cudaGetSymbolAddress((void**)&pq,  g_q);
    cudaGetSymbolAddress((void**)&pkv, g_kv);
    cudaGetSymbolAddress((void**)&pk,  g_k);
    cudaGetSymbolAddress((void**)&pv,  g_v);
    cudaGetSymbolAddress((void**)&pao, g_ao);

    // fold rope weights:  Wq_eff = Wq + Wq_rope ; Wk_eff = Wk_up + Wk_rope
    {
        int n1 = HIDDEN * HIDDEN;
        add2_kernel<<<(n1 + 255) / 256, 256>>>(Wq, Wq_rope, pWq_eff, n1);
        int n2 = LATENT * HIDDEN;
        add2_kernel<<<(n2 + 255) / 256, 256>>>(Wk_up, Wk_rope, pWk_eff, n2);
    }

    dim3 blk(256);
    // q = h @ Wq_eff                      (4096,2048,K=2048)
    sgemm_kernel<<<dim3(HIDDEN / BN, ROWS / BM), blk>>>(
        ROWS, HIDDEN, HIDDEN, h, HIDDEN, pWq_eff, HIDDEN, pq, HIDDEN);
    // kv = h @ Wkv                        (4096,1024,K=2048)
    sgemm_kernel<<<dim3((2 * LATENT) / BN, ROWS / BM), blk>>>(
        ROWS, 2 * LATENT, HIDDEN, h, HIDDEN, Wkv, 2 * LATENT, pkv, 2 * LATENT);
    // k = kv[:, :512] @ Wk_eff            (4096,2048,K=512)
    sgemm_kernel<<<dim3(HIDDEN / BN, ROWS / BM), blk>>>(
        ROWS, HIDDEN, LATENT, pkv, 2 * LATENT, pWk_eff, HIDDEN, pk, HIDDEN);
    // v = kv[:, 512:] @ Wv_up             (4096,2048,K=512)
    sgemm_kernel<<<dim3(HIDDEN / BN, ROWS / BM), blk>>>(
        ROWS, HIDDEN, LATENT, pkv + LATENT, 2 * LATENT, Wv_up, HIDDEN, pv, HIDDEN);

    // attention
    size_t smem = (size_t)(128 * 64 * 2 + 64 * VS_LD + 64 * PS_LD) * sizeof(float);
    cudaFuncSetAttribute(flash_attn_kernel,
                         cudaFuncAttributeMaxDynamicSharedMemorySize, (int)smem);
    flash_attn_kernel<<<dim3(S_LEN / AT_BR, BATCH * NHEADS), blk, smem>>>(
        pq, pk, pv, pao);

    // out = ao @ Wo                       (4096,2048,K=2048)
    sgemm_kernel<<<dim3(HIDDEN / BN, ROWS / BM), blk>>>(
        ROWS, HIDDEN, HIDDEN, pao, HIDDEN, Wo, HIDDEN, out, HIDDEN);
}

// round 2
// speedup vs baseline: 1.3593x; 1.3593x over previous
#include <cuda_runtime.h>
#include <cuda_bf16.h>
#include <cstdint>

// ---------------- problem constants ----------------
#define S_LEN  2048
#define HIDDEN 2048
#define NHEADS 16
#define HD     128
#define LATENT 512
#define BATCH  2
#define ROWS   (BATCH * S_LEN)        // 4096
#define ATT_SCALE 0.088388347648318447f   // 128^-0.5

// ---------------- scratch (static device globals; no allocation) ------------
static __device__ float g_Wq_eff[(size_t)HIDDEN * HIDDEN];   // 16 MB
static __device__ float g_Wk_eff[(size_t)LATENT * HIDDEN];   //  4 MB
static __device__ float g_q  [(size_t)ROWS * HIDDEN];        // 32 MB
static __device__ float g_kv [(size_t)ROWS * (2 * LATENT)];  // 16 MB
static __device__ float g_k  [(size_t)ROWS * HIDDEN];        // 32 MB
static __device__ float g_v  [(size_t)ROWS * HIDDEN];        // 32 MB
static __device__ float g_ao [(size_t)ROWS * HIDDEN];        // 32 MB

// ---------------- elementwise weight fold ----------------
__global__ void add2_kernel(const float* __restrict__ a,
                            const float* __restrict__ b,
                            float* __restrict__ c, int n) {
    int i = blockIdx.x * blockDim.x + threadIdx.x;
    if (i < n) c[i] = a[i] + b[i];
}

// ---------------- fp32 SGEMM (unchanged this round) ----------------
#define BM 128
#define BN 128
#define BK 8

__global__ __launch_bounds__(256)
void sgemm_kernel(int M, int N, int K,
                  const float* __restrict__ A, int lda,
                  const float* __restrict__ B, int ldb,
                  float* __restrict__ C, int ldc)
{
    __shared__ float As[BK][BM];
    __shared__ float Bs[BK][BN + 4];

    const int tid = threadIdx.x;
    const int bm = blockIdx.y * BM;
    const int bn = blockIdx.x * BN;
    const int tr = tid >> 4;
    const int tc = tid & 15;

    const int a_row = tid >> 1;
    const int a_col = (tid & 1) << 2;
    const int b_row = tid >> 5;
    const int b_col = (tid & 31) << 2;

    const float* Aptr = A + (size_t)bm * lda;
    const float* Bptr = B + bn;

    float acc[8][8];
#pragma unroll
    for (int i = 0; i < 8; i++)
#pragma unroll
        for (int j = 0; j < 8; j++) acc[i][j] = 0.f;

    for (int k0 = 0; k0 < K; k0 += BK) {
        float4 av = *(const float4*)(Aptr + (size_t)a_row * lda + k0 + a_col);
        As[a_col + 0][a_row] = av.x;
        As[a_col + 1][a_row] = av.y;
        As[a_col + 2][a_row] = av.z;
        As[a_col + 3][a_row] = av.w;
        float4 bv = *(const float4*)(Bptr + (size_t)(k0 + b_row) * ldb + b_col);
        *(float4*)&Bs[b_row][b_col] = bv;
        __syncthreads();

#pragma unroll
        for (int kk = 0; kk < BK; kk++) {
            float af[8], bf[8];
            *(float4*)&af[0] = *(const float4*)&As[kk][tr * 8];
            *(float4*)&af[4] = *(const float4*)&As[kk][tr * 8 + 4];
            *(float4*)&bf[0] = *(const float4*)&Bs[kk][tc * 8];
            *(float4*)&bf[4] = *(const float4*)&Bs[kk][tc * 8 + 4];
#pragma unroll
            for (int i = 0; i < 8; i++)
#pragma unroll
                for (int j = 0; j < 8; j++)
                    acc[i][j] += af[i] * bf[j];
        }
        __syncthreads();
    }

#pragma unroll
    for (int i = 0; i < 8; i++) {
        float* crow = C + (size_t)(bm + tr * 8 + i) * ldc + bn + tc * 8;
        *(float4*)(crow)     = make_float4(acc[i][0], acc[i][1], acc[i][2], acc[i][3]);
        *(float4*)(crow + 4) = make_float4(acc[i][4], acc[i][5], acc[i][6], acc[i][7]);
    }
}

// ---------------- tf32 helpers ----------------
__device__ __forceinline__ uint32_t f2tf(float x) {
    uint32_t u;
    asm("cvt.rna.tf32.f32 %0, %1;" : "=r"(u) : "f"(x));
    return u;
}

__device__ __forceinline__ void mma_tf32(float* c, const uint32_t* a,
                                         uint32_t b0, uint32_t b1) {
    asm volatile(
        "mma.sync.aligned.m16n8k8.row.col.f32.tf32.tf32.f32 "
        "{%0,%1,%2,%3}, {%4,%5,%6,%7}, {%8,%9}, {%0,%1,%2,%3};"
        : "+f"(c[0]), "+f"(c[1]), "+f"(c[2]), "+f"(c[3])
        : "r"(a[0]), "r"(a[1]), "r"(a[2]), "r"(a[3]), "r"(b0), "r"(b1));
}

// ---------------- tensor-core causal flash attention (tf32 mma) -------------
// Br = 128 (rows/block), Bc = 64 (keys/tile), D = 128. 256 threads = 8 warps.
// Warps: wm = wid>>1 (4 row groups of 32), wn = wid&1.
//  S phase: warp tile 32x32 (2 m-frags x 4 n-frags), k = 128 in steps of 8.
//  PV phase: warp tile 32x64 (2 m-frags x 8 n-frags), k = 64 in steps of 8.
// Softmax: thread t owns row t>>1, half (t&1) (32 cols), partner shuffle xor 1.
#define QS_LD 132
#define KS_LD 132
#define VS_LD 136
#define PS_LD 72

__global__ __launch_bounds__(256, 1)
void flash_attn_tc(const float* __restrict__ Qg,
                   const float* __restrict__ Kg,
                   const float* __restrict__ Vg,
                   float* __restrict__ Og)
{
    extern __shared__ float sm[];
    float* Qs    = sm;                     // 128 x 132 (tf32 bits, pre-scaled)
    float* Ks    = Qs + 128 * QS_LD;       // 64 x 132
    float* Vs    = Ks + 64 * KS_LD;        // 64 x 136
    float* Ps    = Vs + 64 * VS_LD;        // 128 x 72 (S scores then P probs)
    float* rstat = Ps + 128 * PS_LD;       // 128 (corr factor, later 1/l)
    float* Os    = Ks;                     // output staging reuse [128][132]

    const int qt  = (gridDim.x - 1) - blockIdx.x;   // big tiles first
    const int bh  = blockIdx.y;
    const int b   = bh >> 4;
    const int h   = bh & 15;
    const int tid = threadIdx.x;
    const int lane = tid & 31;
    const int wid  = tid >> 5;
    const int wm   = wid >> 1;
    const int wn   = wid & 1;
    const int gid  = lane >> 2;
    const int t4   = lane & 3;

    const float* qbase = Qg + (size_t)(b * S_LEN + qt * 128) * HIDDEN + h * HD;

    // load Q tile (scale + tf32 round)
#pragma unroll
    for (int it = 0; it < 16; it++) {
        int idx = tid + it * 256;           // over 4096 float4
        int r = idx >> 5, c = (idx & 31) << 2;
        float4 v = *(const float4*)(qbase + (size_t)r * HIDDEN + c);
        float* dst = &Qs[r * QS_LD + c];
        dst[0] = __uint_as_float(f2tf(v.x * ATT_SCALE));
        dst[1] = __uint_as_float(f2tf(v.y * ATT_SCALE));
        dst[2] = __uint_as_float(f2tf(v.z * ATT_SCALE));
        dst[3] = __uint_as_float(f2tf(v.w * ATT_SCALE));
    }

    float o[2][8][4];
#pragma unroll
    for (int mi = 0; mi < 2; mi++)
#pragma unroll
        for (int ni = 0; ni < 8; ni++)
#pragma unroll
            for (int x = 0; x < 4; x++) o[mi][ni][x] = 0.f;

    const int srow = tid >> 1;     // softmax row owned
    const int shf  = tid & 1;      // which 32-col half
    float m_i = -1e30f, l_i = 0.f;

    const int nkt = 2 * qt + 2;
    for (int kt = 0; kt < nkt; kt++) {
        // ---- load K,V tile (64 x 128) ----
        const float* kb = Kg + (size_t)(b * S_LEN + kt * 64) * HIDDEN + h * HD;
        const float* vb = Vg + (size_t)(b * S_LEN + kt * 64) * HIDDEN + h * HD;
#pragma unroll
        for (int it = 0; it < 8; it++) {
            int idx = tid + it * 256;       // 2048 float4
            int r = idx >> 5, c = (idx & 31) << 2;
            float4 kv = *(const float4*)(kb + (size_t)r * HIDDEN + c);
            float* kd = &Ks[r * KS_LD + c];
            kd[0] = __uint_as_float(f2tf(kv.x));
            kd[1] = __uint_as_float(f2tf(kv.y));
            kd[2] = __uint_as_float(f2tf(kv.z));
            kd[3] = __uint_as_float(f2tf(kv.w));
            float4 vv = *(const float4*)(vb + (size_t)r * HIDDEN + c);
            float* vd = &Vs[r * VS_LD + c];
            vd[0] = __uint_as_float(f2tf(vv.x));
            vd[1] = __uint_as_float(f2tf(vv.y));
            vd[2] = __uint_as_float(f2tf(vv.z));
            vd[3] = __uint_as_float(f2tf(vv.w));
        }
        __syncthreads();

        // ---- S = Q @ K^T (tensor) ----
        float s[2][4][4];
#pragma unroll
        for (int mi = 0; mi < 2; mi++)
#pragma unroll
            for (int ni = 0; ni < 4; ni++)
#pragma unroll
                for (int x = 0; x < 4; x++) s[mi][ni][x] = 0.f;

#pragma unroll 4
        for (int k0 = 0; k0 < 128; k0 += 8) {
            uint32_t a[2][4];
#pragma unroll
            for (int mi = 0; mi < 2; mi++) {
                int r0 = wm * 32 + mi * 16;
                a[mi][0] = __float_as_uint(Qs[(r0 + gid)     * QS_LD + k0 + t4]);
                a[mi][1] = __float_as_uint(Qs[(r0 + gid + 8) * QS_LD + k0 + t4]);
                a[mi][2] = __float_as_uint(Qs[(r0 + gid)     * QS_LD + k0 + t4 + 4]);
                a[mi][3] = __float_as_uint(Qs[(r0 + gid + 8) * QS_LD + k0 + t4 + 4]);
            }
#pragma unroll
            for (int ni = 0; ni < 4; ni++) {
                int c0 = wn * 32 + ni * 8;
                uint32_t b0 = __float_as_uint(Ks[(c0 + gid) * KS_LD + k0 + t4]);
                uint32_t b1 = __float_as_uint(Ks[(c0 + gid) * KS_LD + k0 + t4 + 4]);
#pragma unroll
                for (int mi = 0; mi < 2; mi++)
                    mma_tf32(s[mi][ni], a[mi], b0, b1);
            }
        }

        // dump S fragments to smem
#pragma unroll
        for (int mi = 0; mi < 2; mi++) {
            int r0 = wm * 32 + mi * 16;
#pragma unroll
            for (int ni = 0; ni < 4; ni++) {
                int c0 = wn * 32 + ni * 8 + 2 * t4;
                *(float2*)&Ps[(r0 + gid)     * PS_LD + c0] = make_float2(s[mi][ni][0], s[mi][ni][1]);
                *(float2*)&Ps[(r0 + gid + 8) * PS_LD + c0] = make_float2(s[mi][ni][2], s[mi][ni][3]);
            }
        }
        __syncthreads();

        // ---- online softmax (2 threads per row) ----
        {
            float sv[32];
#pragma unroll
            for (int j4 = 0; j4 < 8; j4++)
                *(float4*)&sv[j4 * 4] = *(const float4*)&Ps[srow * PS_LD + shf * 32 + j4 * 4];

            const bool diag = (kt >= 2 * qt);
            const int qr  = qt * 128 + srow;
            const int kc0 = kt * 64 + shf * 32;
            float mloc = -1e30f;
#pragma unroll
            for (int j = 0; j < 32; j++) {
                if (diag && (kc0 + j > qr)) sv[j] = -1e30f;   // masked -> p = 0
                mloc = fmaxf(mloc, sv[j]);
            }
            mloc = fmaxf(mloc, __shfl_xor_sync(0xffffffffu, mloc, 1));
            float mnew = fmaxf(m_i, mloc);
            float corr = __expf(m_i - mnew);
            float rs = 0.f;
#pragma unroll
            for (int j = 0; j < 32; j++) {
                float p = __expf(sv[j] - mnew);
                sv[j] = p;
                rs += p;
            }
            rs += __shfl_xor_sync(0xffffffffu, rs, 1);
            l_i = l_i * corr + rs;
            m_i = mnew;
#pragma unroll
            for (int j4 = 0; j4 < 8; j4++) {
                float4 pw;
                pw.x = __uint_as_float(f2tf(sv[j4 * 4 + 0]));
                pw.y = __uint_as_float(f2tf(sv[j4 * 4 + 1]));
                pw.z = __uint_as_float(f2tf(sv[j4 * 4 + 2]));
                pw.w = __uint_as_float(f2tf(sv[j4 * 4 + 3]));
                *(float4*)&Ps[srow * PS_LD + shf * 32 + j4 * 4] = pw;
            }
            if (shf == 0) rstat[srow] = corr;
        }
        __syncthreads();

        // ---- O = O*corr + P @ V (tensor) ----
#pragma unroll
        for (int mi = 0; mi < 2; mi++) {
            int r0 = wm * 32 + mi * 16;
            float clo = rstat[r0 + gid];
            float chi = rstat[r0 + gid + 8];
#pragma unroll
            for (int ni = 0; ni < 8; ni++) {
                o[mi][ni][0] *= clo; o[mi][ni][1] *= clo;
                o[mi][ni][2] *= chi; o[mi][ni][3] *= chi;
            }
        }
#pragma unroll 2
        for (int k0 = 0; k0 < 64; k0 += 8) {
            uint32_t a[2][4];
#pragma unroll
            for (int mi = 0; mi < 2; mi++) {
                int r0 = wm * 32 + mi * 16;
                a[mi][0] = __float_as_uint(Ps[(r0 + gid)     * PS_LD + k0 + t4]);
                a[mi][1] = __float_as_uint(Ps[(r0 + gid + 8) * PS_LD + k0 + t4]);
                a[mi][2] = __float_as_uint(Ps[(r0 + gid)     * PS_LD + k0 + t4 + 4]);
                a[mi][3] = __float_as_uint(Ps[(r0 + gid + 8) * PS_LD + k0 + t4 + 4]);
            }
#pragma unroll
            for (int ni = 0; ni < 8; ni++) {
                int n0 = wn * 64 + ni * 8;
                uint32_t b0 = __float_as_uint(Vs[(k0 + t4)     * VS_LD + n0 + gid]);
                uint32_t b1 = __float_as_uint(Vs[(k0 + t4 + 4) * VS_LD + n0 + gid]);
#pragma unroll
                for (int mi = 0; mi < 2; mi++)
                    mma_tf32(o[mi][ni], a[mi], b0, b1);
            }
        }
        __syncthreads();
    }

    // ---- finalize: 1/l, stage O, coalesced write ----
    if (shf == 0) rstat[srow] = 1.f / l_i;
    __syncthreads();
#pragma unroll
    for (int mi = 0; mi < 2; mi++) {
        int r0 = wm * 32 + mi * 16;
        float llo = rstat[r0 + gid];
        float lhi = rstat[r0 + gid + 8];
#pragma unroll
        for (int ni = 0; ni < 8; ni++) {
            int n0 = wn * 64 + ni * 8 + 2 * t4;
            *(float2*)&Os[(r0 + gid)     * QS_LD + n0] =
                make_float2(o[mi][ni][0] * llo, o[mi][ni][1] * llo);
            *(float2*)&Os[(r0 + gid + 8) * QS_LD + n0] =
                make_float2(o[mi][ni][2] * lhi, o[mi][ni][3] * lhi);
        }
    }
    __syncthreads();

    float* og = Og + (size_t)(b * S_LEN + qt * 128) * HIDDEN + h * HD;
#pragma unroll
    for (int it = 0; it < 16; it++) {
        int idx = tid + it * 256;
        int r = idx >> 5, c = (idx & 31) << 2;
        *(float4*)(og + (size_t)r * HIDDEN + c) = *(const float4*)&Os[r * QS_LD + c];
    }
}

// ---------------- launch ----------------
extern "C" void kernel_launch(void* const* d_in, const int* in_sizes, int n_in,
                              void* d_out, int out_size)
{
    const float* h       = (const float*)d_in[0];
    const float* Wq      = (const float*)d_in[3];
    const float* Wkv     = (const float*)d_in[4];
    const float* Wk_up   = (const float*)d_in[5];
    const float* Wv_up   = (const float*)d_in[6];
    const float* Wq_rope = (const float*)d_in[7];
    const float* Wk_rope = (const float*)d_in[8];
    const float* Wo      = (const float*)d_in[9];
    float* out = (float*)d_out;

    float *pWq_eff, *pWk_eff, *pq, *pkv, *pk, *pv, *pao;
    cudaGetSymbolAddress((void**)&pWq_eff, g_Wq_eff);
    cudaGetSymbolAddress((void**)&pWk_eff, g_Wk_eff);
    cudaGetSymbolAddress((void**)&pq,  g_q);
    cudaGetSymbolAddress((void**)&pkv, g_kv);
    cudaGetSymbolAddress((void**)&pk,  g_k);
    cudaGetSymbolAddress((void**)&pv,  g_v);
    cudaGetSymbolAddress((void**)&pao, g_ao);

    {
        int n1 = HIDDEN * HIDDEN;
        add2_kernel<<<(n1 + 255) / 256, 256>>>(Wq, Wq_rope, pWq_eff, n1);
        int n2 = LATENT * HIDDEN;
        add2_kernel<<<(n2 + 255) / 256, 256>>>(Wk_up, Wk_rope, pWk_eff, n2);
    }

    dim3 blk(256);
    sgemm_kernel<<<dim3(HIDDEN / BN, ROWS / BM), blk>>>(
        ROWS, HIDDEN, HIDDEN, h, HIDDEN, pWq_eff, HIDDEN, pq, HIDDEN);
    sgemm_kernel<<<dim3((2 * LATENT) / BN, ROWS / BM), blk>>>(
        ROWS, 2 * LATENT, HIDDEN, h, HIDDEN, Wkv, 2 * LATENT, pkv, 2 * LATENT);
    sgemm_kernel<<<dim3(HIDDEN / BN, ROWS / BM), blk>>>(
        ROWS, HIDDEN, LATENT, pkv, 2 * LATENT, pWk_eff, HIDDEN, pk, HIDDEN);
    sgemm_kernel<<<dim3(HIDDEN / BN, ROWS / BM), blk>>>(
        ROWS, HIDDEN, LATENT, pkv + LATENT, 2 * LATENT, Wv_up, HIDDEN, pv, HIDDEN);

    // attention (tensor-core tf32)
    size_t smem = (size_t)(128 * QS_LD + 64 * KS_LD + 64 * VS_LD +
                           128 * PS_LD + 128) * sizeof(float);
    cudaFuncSetAttribute(flash_attn_tc,
                         cudaFuncAttributeMaxDynamicSharedMemorySize, (int)smem);
    flash_attn_tc<<<dim3(S_LEN / 128, BATCH * NHEADS), blk, smem>>>(
        pq, pk, pv, pao);

    sgemm_kernel<<<dim3(HIDDEN / BN, ROWS / BM), blk>>>(
        ROWS, HIDDEN, HIDDEN, pao, HIDDEN, Wo, HIDDEN, out, HIDDEN);
}

// round 3
// speedup vs baseline: 3.8857x; 2.8586x over previous
#include <cuda_runtime.h>
#include <cuda_bf16.h>
#include <cstdint>

// ---------------- problem constants ----------------
#define S_LEN  2048
#define HIDDEN 2048
#define NHEADS 16
#define HD     128
#define LATENT 512
#define BATCH  2
#define ROWS   (BATCH * S_LEN)        // 4096
#define ATT_SCALE 0.088388347648318447f

// ---------------- scratch ----------------
static __device__ float g_Wq_eff[(size_t)HIDDEN * HIDDEN];
static __device__ float g_Wk_eff[(size_t)LATENT * HIDDEN];
static __device__ float g_q  [(size_t)ROWS * HIDDEN];
static __device__ float g_kv [(size_t)ROWS * (2 * LATENT)];
static __device__ float g_k  [(size_t)ROWS * HIDDEN];
static __device__ float g_v  [(size_t)ROWS * HIDDEN];
static __device__ float g_ao [(size_t)ROWS * HIDDEN];

__global__ void add2_kernel(const float* __restrict__ a,
                            const float* __restrict__ b,
                            float* __restrict__ c, int n) {
    int i = blockIdx.x * blockDim.x + threadIdx.x;
    if (i < n) c[i] = a[i] + b[i];
}

// ---------------- tf32 helpers ----------------
__device__ __forceinline__ uint32_t f2tf(float x) {
    uint32_t u;
    asm("cvt.rna.tf32.f32 %0, %1;" : "=r"(u) : "f"(x));
    return u;
}
__device__ __forceinline__ float f2tff(float x) {
    return __uint_as_float(f2tf(x));
}
__device__ __forceinline__ void mma_tf32(float* c, const uint32_t* a,
                                         uint32_t b0, uint32_t b1) {
    asm volatile(
        "mma.sync.aligned.m16n8k8.row.col.f32.tf32.tf32.f32 "
        "{%0,%1,%2,%3}, {%4,%5,%6,%7}, {%8,%9}, {%0,%1,%2,%3};"
        : "+f"(c[0]), "+f"(c[1]), "+f"(c[2]), "+f"(c[3])
        : "r"(a[0]), "r"(a[1]), "r"(a[2]), "r"(a[3]), "r"(b0), "r"(b1));
}
__device__ __forceinline__ void cp_async16(void* dst_smem, const void* src) {
    uint32_t d = (uint32_t)__cvta_generic_to_shared(dst_smem);
    asm volatile("cp.async.cg.shared.global [%0], [%1], 16;" :: "r"(d), "l"(src));
}
__device__ __forceinline__ void cp_commit() {
    asm volatile("cp.async.commit_group;");
}
__device__ __forceinline__ void cp_wait_all() {
    asm volatile("cp.async.wait_group 0;");
}

// =======================================================================
// tf32 tensor-core GEMM: C[M,N] = (A[M,K] @ B[K,N]) * scale  (opt tf32-round)
// Block tile 256x128, BK=16, 256 threads (8 warps, 4x2), warp tile 64x64.
// Double-buffered smem, register-prefetch of global tiles.
// =======================================================================
#define GBM 256
#define GBN 128
#define GBK 16
#define ALD 20
#define BLD 136
#define G_SMEM_FLOATS (2 * GBM * ALD + 2 * GBK * BLD)

__global__ __launch_bounds__(256, 1)
void gemm_tf32(int M, int N, int K,
               const float* __restrict__ A, int lda,
               const float* __restrict__ B, int ldb,
               float* __restrict__ C, int ldc,
               float scale, int round_out)
{
    extern __shared__ float gsm[];
    float* As = gsm;                       // [2][256][20]
    float* Bs = gsm + 2 * GBM * ALD;       // [2][16][136]

    const int tid  = threadIdx.x;
    const int lane = tid & 31;
    const int wid  = tid >> 5;
    const int gid  = lane >> 2;
    const int t4   = lane & 3;
    const int wm   = wid >> 1;             // 0..3
    const int wn   = wid & 1;              // 0..1
    const int bm   = blockIdx.y * GBM;
    const int bn   = blockIdx.x * GBN;

    // A loader: 4 float4/thread: row = tid/4 + i*64, col4 = (tid&3)*4
    const int a_r0 = tid >> 2;
    const int a_c  = (tid & 3) << 2;
    // B loader: 2 float4/thread: row = tid/32 + i*8, col4 = (tid&31)*4
    const int b_r0 = tid >> 5;
    const int b_c  = (tid & 31) << 2;

    float4 pa[4], pb[2];

    auto load_g = [&](int kt) {
        const float* Ab = A + (size_t)bm * lda + kt * GBK;
#pragma unroll
        for (int i = 0; i < 4; i++)
            pa[i] = *(const float4*)(Ab + (size_t)(a_r0 + i * 64) * lda + a_c);
        const float* Bb = B + (size_t)(kt * GBK) * ldb + bn;
#pragma unroll
        for (int i = 0; i < 2; i++)
            pb[i] = *(const float4*)(Bb + (size_t)(b_r0 + i * 8) * ldb + b_c);
    };
    auto store_s = [&](int buf) {
        float* Ad = As + buf * (GBM * ALD);
#pragma unroll
        for (int i = 0; i < 4; i++) {
            float* p = Ad + (a_r0 + i * 64) * ALD + a_c;
            p[0] = f2tff(pa[i].x); p[1] = f2tff(pa[i].y);
            p[2] = f2tff(pa[i].z); p[3] = f2tff(pa[i].w);
        }
        float* Bd = Bs + buf * (GBK * BLD);
#pragma unroll
        for (int i = 0; i < 2; i++) {
            float* p = Bd + (b_r0 + i * 8) * BLD + b_c;
            p[0] = f2tff(pb[i].x); p[1] = f2tff(pb[i].y);
            p[2] = f2tff(pb[i].z); p[3] = f2tff(pb[i].w);
        }
    };

    float acc[4][8][4];
#pragma unroll
    for (int mi = 0; mi < 4; mi++)
#pragma unroll
        for (int ni = 0; ni < 8; ni++)
#pragma unroll
            for (int x = 0; x < 4; x++) acc[mi][ni][x] = 0.f;

    load_g(0);
    store_s(0);
    __syncthreads();

    const int nk = K / GBK;
    for (int kt = 0; kt < nk; kt++) {
        const int buf = kt & 1;
        if (kt + 1 < nk) load_g(kt + 1);

        const float* Ab = As + buf * (GBM * ALD);
        const float* Bb = Bs + buf * (GBK * BLD);
#pragma unroll
        for (int ks = 0; ks < 2; ks++) {
            const int k0 = ks * 8;
            uint32_t af[4][4];
#pragma unroll
            for (int mi = 0; mi < 4; mi++) {
                int r = wm * 64 + mi * 16;
                af[mi][0] = __float_as_uint(Ab[(r + gid)     * ALD + k0 + t4]);
                af[mi][1] = __float_as_uint(Ab[(r + gid + 8) * ALD + k0 + t4]);
                af[mi][2] = __float_as_uint(Ab[(r + gid)     * ALD + k0 + t4 + 4]);
                af[mi][3] = __float_as_uint(Ab[(r + gid + 8) * ALD + k0 + t4 + 4]);
            }
#pragma unroll
            for (int ni = 0; ni < 8; ni++) {
                int n0 = wn * 64 + ni * 8;
                uint32_t b0 = __float_as_uint(Bb[(k0 + t4)     * BLD + n0 + gid]);
                uint32_t b1 = __float_as_uint(Bb[(k0 + t4 + 4) * BLD + n0 + gid]);
#pragma unroll
                for (int mi = 0; mi < 4; mi++)
                    mma_tf32(acc[mi][ni], af[mi], b0, b1);
            }
        }
        if (kt + 1 < nk) store_s(buf ^ 1);
        __syncthreads();
    }

    // epilogue
#pragma unroll
    for (int mi = 0; mi < 4; mi++) {
        int row = bm + wm * 64 + mi * 16 + gid;
#pragma unroll
        for (int ni = 0; ni < 8; ni++) {
            int col = bn + wn * 64 + ni * 8 + 2 * t4;
            float v0 = acc[mi][ni][0] * scale;
            float v1 = acc[mi][ni][1] * scale;
            float v2 = acc[mi][ni][2] * scale;
            float v3 = acc[mi][ni][3] * scale;
            if (round_out) {
                v0 = f2tff(v0); v1 = f2tff(v1); v2 = f2tff(v2); v3 = f2tff(v3);
            }
            *(float2*)(C + (size_t)row * ldc + col)       = make_float2(v0, v1);
            *(float2*)(C + (size_t)(row + 8) * ldc + col) = make_float2(v2, v3);
        }
    }
}

// =======================================================================
// Flash attention, register-resident softmax.
// Br=128 (8 warps x 16 rows), Bc=64, D=128. 256 threads, 1 block/SM.
// Q/K/V in gmem are already tf32-rounded (Q also pre-scaled).
// K,V double-buffered via cp.async. S & P never leave registers.
// =======================================================================
#define QLD 132
#define KLD 132
#define VLD 136
#define FA_STG (64 * KLD + 64 * VLD)                       // 17152 floats
#define FA_SMEM_FLOATS (128 * QLD + 2 * FA_STG)            // 51200 floats

__global__ __launch_bounds__(256, 1)
void flash_attn_reg(const float* __restrict__ Qg,
                    const float* __restrict__ Kg,
                    const float* __restrict__ Vg,
                    float* __restrict__ Og)
{
    extern __shared__ float sm[];
    float* Qs   = sm;                       // [128][132]
    float* Stg0 = sm + 128 * QLD;           // 2 stages of K[64][132] + V[64][136]

    const int qt   = (gridDim.x - 1) - blockIdx.x;   // big tiles first
    const int bh   = blockIdx.y;
    const int b    = bh >> 4;
    const int h    = bh & 15;
    const int tid  = threadIdx.x;
    const int lane = tid & 31;
    const int wid  = tid >> 5;
    const int gid  = lane >> 2;
    const int t4   = lane & 3;

    const float* qb = Qg + (size_t)(b * S_LEN + qt * 128) * HIDDEN + h * HD;

    // Q tile -> smem (plain copy, already tf32+scaled)
#pragma unroll
    for (int it = 0; it < 16; it++) {
        int idx = tid + it * 256;
        int r = idx >> 5, c = (idx & 31) << 2;
        *(float4*)&Qs[r * QLD + c] = *(const float4*)(qb + (size_t)r * HIDDEN + c);
    }

    // K/V stage loader via cp.async
    const int kv_r0 = tid >> 5;
    const int kv_c  = (tid & 31) << 2;
    auto load_kv = [&](int kt, int buf) {
        float* Kd = Stg0 + buf * FA_STG;
        float* Vd = Kd + 64 * KLD;
        const float* kb = Kg + (size_t)(b * S_LEN + kt * 64) * HIDDEN + h * HD;
        const float* vb = Vg + (size_t)(b * S_LEN + kt * 64) * HIDDEN + h * HD;
#pragma unroll
        for (int i = 0; i < 8; i++) {
            int r = kv_r0 + i * 8;
            cp_async16(&Kd[r * KLD + kv_c], kb + (size_t)r * HIDDEN + kv_c);
            cp_async16(&Vd[r * VLD + kv_c], vb + (size_t)r * HIDDEN + kv_c);
        }
        cp_commit();
    };

    load_kv(0, 0);

    float o[16][4];
#pragma unroll
    for (int ni = 0; ni < 16; ni++)
#pragma unroll
        for (int x = 0; x < 4; x++) o[ni][x] = 0.f;
    float m_lo = -1e30f, m_hi = -1e30f, l_lo = 0.f, l_hi = 0.f;

    const int r0      = wid * 16;
    const int row_lo  = qt * 128 + r0 + gid;
    const int row_hi  = row_lo + 8;
    const int nkt     = 2 * qt + 2;

    for (int kt = 0; kt < nkt; kt++) {
        const int buf = kt & 1;
        cp_wait_all();
        __syncthreads();
        if (kt + 1 < nkt) load_kv(kt + 1, buf ^ 1);

        const float* Kb = Stg0 + buf * FA_STG;
        const float* Vb = Kb + 64 * KLD;

        // ---- S = Q @ K^T ----
        float s[8][4];
#pragma unroll
        for (int ni = 0; ni < 8; ni++)
#pragma unroll
            for (int x = 0; x < 4; x++) s[ni][x] = 0.f;

#pragma unroll
        for (int k8 = 0; k8 < 16; k8++) {
            const int k0 = k8 * 8;
            uint32_t a[4];
            a[0] = __float_as_uint(Qs[(r0 + gid)     * QLD + k0 + t4]);
            a[1] = __float_as_uint(Qs[(r0 + gid + 8) * QLD + k0 + t4]);
            a[2] = __float_as_uint(Qs[(r0 + gid)     * QLD + k0 + t4 + 4]);
            a[3] = __float_as_uint(Qs[(r0 + gid + 8) * QLD + k0 + t4 + 4]);
#pragma unroll
            for (int ni = 0; ni < 8; ni++) {
                uint32_t b0 = __float_as_uint(Kb[(ni * 8 + gid) * KLD + k0 + t4]);
                uint32_t b1 = __float_as_uint(Kb[(ni * 8 + gid) * KLD + k0 + t4 + 4]);
                mma_tf32(s[ni], a, b0, b1);
            }
        }

        // ---- causal mask (only the last two tiles can cross the diagonal) ----
        if (kt >= 2 * qt) {
            const int cb = kt * 64 + 2 * t4;
#pragma unroll
            for (int ni = 0; ni < 8; ni++) {
                int c0 = cb + ni * 8;
                if (c0     > row_lo) s[ni][0] = -1e30f;
                if (c0 + 1 > row_lo) s[ni][1] = -1e30f;
                if (c0     > row_hi) s[ni][2] = -1e30f;
                if (c0 + 1 > row_hi) s[ni][3] = -1e30f;
            }
        }

        // ---- online softmax, all in registers (quad = one row pair) ----
        float mlo = -1e30f, mhi = -1e30f;
#pragma unroll
        for (int ni = 0; ni < 8; ni++) {
            mlo = fmaxf(mlo, fmaxf(s[ni][0], s[ni][1]));
            mhi = fmaxf(mhi, fmaxf(s[ni][2], s[ni][3]));
        }
        mlo = fmaxf(mlo, __shfl_xor_sync(0xffffffffu, mlo, 1));
        mlo = fmaxf(mlo, __shfl_xor_sync(0xffffffffu, mlo, 2));
        mhi = fmaxf(mhi, __shfl_xor_sync(0xffffffffu, mhi, 1));
        mhi = fmaxf(mhi, __shfl_xor_sync(0xffffffffu, mhi, 2));

        float mnl = fmaxf(m_lo, mlo), mnh = fmaxf(m_hi, mhi);
        float clo = __expf(m_lo - mnl), chi = __expf(m_hi - mnh);
        m_lo = mnl; m_hi = mnh;

        float rlo = 0.f, rhi = 0.f;
#pragma unroll
        for (int ni = 0; ni < 8; ni++) {
            float p0 = __expf(s[ni][0] - mnl);
            float p1 = __expf(s[ni][1] - mnl);
            float p2 = __expf(s[ni][2] - mnh);
            float p3 = __expf(s[ni][3] - mnh);
            rlo += p0 + p1; rhi += p2 + p3;
            s[ni][0] = f2tff(p0); s[ni][1] = f2tff(p1);
            s[ni][2] = f2tff(p2); s[ni][3] = f2tff(p3);
        }
        rlo += __shfl_xor_sync(0xffffffffu, rlo, 1);
        rlo += __shfl_xor_sync(0xffffffffu, rlo, 2);
        rhi += __shfl_xor_sync(0xffffffffu, rhi, 1);
        rhi += __shfl_xor_sync(0xffffffffu, rhi, 2);
        l_lo = l_lo * clo + rlo;
        l_hi = l_hi * chi + rhi;

        // rescale O accumulators
#pragma unroll
        for (int ni = 0; ni < 16; ni++) {
            o[ni][0] *= clo; o[ni][1] *= clo;
            o[ni][2] *= chi; o[ni][3] *= chi;
        }

        // ---- O += P @ V : build A-frags from S frags via quad shuffles ----
        const int qbase = lane & ~3;
        const int sA = qbase | (t4 >> 1);
        const int sB = qbase | ((t4 >> 1) + 2);
        const bool odd = (t4 & 1);
#pragma unroll
        for (int kc = 0; kc < 8; kc++) {
            float v0 = __shfl_sync(0xffffffffu, s[kc][0], sA);
            float v1 = __shfl_sync(0xffffffffu, s[kc][1], sA);
            float v2 = __shfl_sync(0xffffffffu, s[kc][2], sA);
            float v3 = __shfl_sync(0xffffffffu, s[kc][3], sA);
            float w0 = __shfl_sync(0xffffffffu, s[kc][0], sB);
            float w1 = __shfl_sync(0xffffffffu, s[kc][1], sB);
            float w2 = __shfl_sync(0xffffffffu, s[kc][2], sB);
            float w3 = __shfl_sync(0xffffffffu, s[kc][3], sB);
            uint32_t a[4];
            a[0] = __float_as_uint(odd ? v1 : v0);
            a[1] = __float_as_uint(odd ? v3 : v2);
            a[2] = __float_as_uint(odd ? w1 : w0);
            a[3] = __float_as_uint(odd ? w3 : w2);
#pragma unroll
            for (int ni = 0; ni < 16; ni++) {
                uint32_t b0 = __float_as_uint(Vb[(kc * 8 + t4)     * VLD + ni * 8 + gid]);
                uint32_t b1 = __float_as_uint(Vb[(kc * 8 + t4 + 4) * VLD + ni * 8 + gid]);
                mma_tf32(o[ni], a, b0, b1);
            }
        }
        __syncthreads();
    }

    // ---- normalize + write ----
    const float il0 = 1.f / l_lo, il1 = 1.f / l_hi;
    float* olo = Og + (size_t)(b * S_LEN + row_lo) * HIDDEN + h * HD;
    float* ohi = Og + (size_t)(b * S_LEN + row_hi) * HIDDEN + h * HD;
#pragma unroll
    for (int ni = 0; ni < 16; ni++) {
        int col = ni * 8 + 2 * t4;
        *(float2*)(olo + col) = make_float2(o[ni][0] * il0, o[ni][1] * il0);
        *(float2*)(ohi + col) = make_float2(o[ni][2] * il1, o[ni][3] * il1);
    }
}

// ---------------- launch ----------------
extern "C" void kernel_launch(void* const* d_in, const int* in_sizes, int n_in,
                              void* d_out, int out_size)
{
    const float* h       = (const float*)d_in[0];
    const float* Wq      = (const float*)d_in[3];
    const float* Wkv     = (const float*)d_in[4];
    const float* Wk_up   = (const float*)d_in[5];
    const float* Wv_up   = (const float*)d_in[6];
    const float* Wq_rope = (const float*)d_in[7];
    const float* Wk_rope = (const float*)d_in[8];
    const float* Wo      = (const float*)d_in[9];
    float* out = (float*)d_out;

    float *pWq_eff, *pWk_eff, *pq, *pkv, *pk, *pv, *pao;
    cudaGetSymbolAddress((void**)&pWq_eff, g_Wq_eff);
    cudaGetSymbolAddress((void**)&pWk_eff, g_Wk_eff);
    cudaGetSymbolAddress((void**)&pq,  g_q);
    cudaGetSymbolAddress((void**)&pkv, g_kv);
    cudaGetSymbolAddress((void**)&pk,  g_k);
    cudaGetSymbolAddress((void**)&pv,  g_v);
    cudaGetSymbolAddress((void**)&pao, g_ao);

    static int attr_done = 0;
    const int g_smem  = G_SMEM_FLOATS * sizeof(float);     // 58368
    const int fa_smem = FA_SMEM_FLOATS * sizeof(float);    // 204800
    if (!attr_done) {
        cudaFuncSetAttribute(gemm_tf32,
            cudaFuncAttributeMaxDynamicSharedMemorySize, g_smem);
        cudaFuncSetAttribute(flash_attn_reg,
            cudaFuncAttributeMaxDynamicSharedMemorySize, fa_smem);
        attr_done = 1;
    }

    {
        int n1 = HIDDEN * HIDDEN;
        add2_kernel<<<(n1 + 255) / 256, 256>>>(Wq, Wq_rope, pWq_eff, n1);
        int n2 = LATENT * HIDDEN;
        add2_kernel<<<(n2 + 255) / 256, 256>>>(Wk_up, Wk_rope, pWk_eff, n2);
    }

    dim3 blk(256);
    // q = tf32(scale * h @ Wq_eff)
    gemm_tf32<<<dim3(HIDDEN / GBN, ROWS / GBM), blk, g_smem>>>(
        ROWS, HIDDEN, HIDDEN, h, HIDDEN, pWq_eff, HIDDEN, pq, HIDDEN,
        ATT_SCALE, 1);
    // kv = h @ Wkv (raw fp32)
    gemm_tf32<<<dim3((2 * LATENT) / GBN, ROWS / GBM), blk, g_smem>>>(
        ROWS, 2 * LATENT, HIDDEN, h, HIDDEN, Wkv, 2 * LATENT, pkv, 2 * LATENT,
        1.f, 0);
    // k = tf32(kv[:, :512] @ Wk_eff)
    gemm_tf32<<<dim3(HIDDEN / GBN, ROWS / GBM), blk, g_smem>>>(
        ROWS, HIDDEN, LATENT, pkv, 2 * LATENT, pWk_eff, HIDDEN, pk, HIDDEN,
        1.f, 1);
    // v = tf32(kv[:, 512:] @ Wv_up)
    gemm_tf32<<<dim3(HIDDEN / GBN, ROWS / GBM), blk, g_smem>>>(
        ROWS, HIDDEN, LATENT, pkv + LATENT, 2 * LATENT, Wv_up, HIDDEN, pv, HIDDEN,
        1.f, 1);

    // attention
    flash_attn_reg<<<dim3(S_LEN / 128, BATCH * NHEADS), blk, fa_smem>>>(
        pq, pk, pv, pao);

    // out = ao @ Wo
    gemm_tf32<<<dim3(HIDDEN / GBN, ROWS / GBM), blk, g_smem>>>(
        ROWS, HIDDEN, HIDDEN, pao, HIDDEN, Wo, HIDDEN, out, HIDDEN,
        1.f, 0);
}

// round 4
// speedup vs baseline: 7.4863x; 1.9267x over previous
#include <cuda_runtime.h>
#include <cuda_fp16.h>
#include <cstdint>

// ---------------- problem constants ----------------
#define S_LEN  2048
#define HIDDEN 2048
#define NHEADS 16
#define HD     128
#define LATENT 512
#define BATCH  2
#define ROWS   (BATCH * S_LEN)           // 4096
// 128^-0.5 * log2(e)  (fold exp->exp2)
#define QK_SCALE 0.12751745f

// ---------------- scratch (static device globals) ----------------
static __device__ __half g_h16 [(size_t)ROWS * HIDDEN];
static __device__ __half g_WqT [(size_t)HIDDEN * HIDDEN];
static __device__ __half g_WkvT[(size_t)(2 * LATENT) * HIDDEN];
static __device__ __half g_WkT [(size_t)HIDDEN * LATENT];
static __device__ __half g_WvT [(size_t)HIDDEN * LATENT];
static __device__ __half g_WoT [(size_t)HIDDEN * HIDDEN];
static __device__ __half g_q16 [(size_t)ROWS * HIDDEN];
static __device__ __half g_kv16[(size_t)ROWS * (2 * LATENT)];
static __device__ __half g_k16 [(size_t)ROWS * HIDDEN];
static __device__ __half g_vt16[(size_t)HIDDEN * ROWS];    // [col][token]
static __device__ __half g_ao16[(size_t)ROWS * HIDDEN];

// ---------------- asm helpers ----------------
__device__ __forceinline__ void mma_h(float* c, const uint32_t* a,
                                      uint32_t b0, uint32_t b1) {
    asm volatile(
        "mma.sync.aligned.m16n8k16.row.col.f32.f16.f16.f32 "
        "{%0,%1,%2,%3}, {%4,%5,%6,%7}, {%8,%9}, {%0,%1,%2,%3};"
        : "+f"(c[0]), "+f"(c[1]), "+f"(c[2]), "+f"(c[3])
        : "r"(a[0]), "r"(a[1]), "r"(a[2]), "r"(a[3]), "r"(b0), "r"(b1));
}
__device__ __forceinline__ void ldsm_x4(uint32_t& r0, uint32_t& r1,
                                        uint32_t& r2, uint32_t& r3,
                                        uint32_t addr) {
    asm volatile("ldmatrix.sync.aligned.m8n8.x4.shared.b16 {%0,%1,%2,%3}, [%4];"
                 : "=r"(r0), "=r"(r1), "=r"(r2), "=r"(r3) : "r"(addr));
}
__device__ __forceinline__ void cp16(uint32_t dst, const void* src) {
    asm volatile("cp.async.cg.shared.global [%0], [%1], 16;" :: "r"(dst), "l"(src));
}
__device__ __forceinline__ void cp_commit() {
    asm volatile("cp.async.commit_group;");
}
__device__ __forceinline__ void cp_wait1() {
    asm volatile("cp.async.wait_group 1;");
}
__device__ __forceinline__ uint32_t h2pack(float hi, float lo) {
    uint32_t r;
    asm("cvt.rn.f16x2.f32 %0, %1, %2;" : "=r"(r) : "f"(hi), "f"(lo));
    return r;
}

// ---------------- pre-pass kernels ----------------
__global__ void cvt_f2h(const float* __restrict__ a, __half* __restrict__ o, int n) {
    int idx = (blockIdx.x * blockDim.x + threadIdx.x) * 4;
    if (idx < n) {
        float4 v = *(const float4*)(a + idx);
        __half2* p = (__half2*)(o + idx);
        p[0] = __floats2half2_rn(v.x, v.y);
        p[1] = __floats2half2_rn(v.z, v.w);
    }
}

// out[n][k] = (a[k][n] (+ a2[k][n])) as fp16;  a is [K][N]
__global__ void transpose_cvt(const float* __restrict__ a,
                              const float* __restrict__ a2,
                              __half* __restrict__ o, int K, int N) {
    __shared__ float t[32][33];
    int k0 = blockIdx.y * 32, n0 = blockIdx.x * 32;
    int x = threadIdx.x, y = threadIdx.y;
#pragma unroll
    for (int i = 0; i < 4; i++) {
        int k = k0 + y + 8 * i;
        float v = a[(size_t)k * N + n0 + x];
        if (a2) v += a2[(size_t)k * N + n0 + x];
        t[y + 8 * i][x] = v;
    }
    __syncthreads();
#pragma unroll
    for (int i = 0; i < 4; i++) {
        int n = n0 + y + 8 * i;
        o[(size_t)n * K + k0 + x] = __float2half_rn(t[x][y + 8 * i]);
    }
}

// =======================================================================
// fp16 tensor-core GEMM: C = (A[M,K] @ Bt[N,K]^T) * scale
// 256x128 tile, BK=32, 256 threads (8 warps 4x2, warp 64x64), 3-stage cp.async.
// mode 0: C fp32 [M][N]; mode 1: C fp16 [M][N]; mode 2: C fp16 [N][M].
// =======================================================================
#define GBM 256
#define GBN 128
#define GBK 32
#define ALD 40
#define BLD 40
#define STG_A (GBM * ALD)
#define STG_B (GBN * BLD)
#define STG_SZ (STG_A + STG_B)
#define G_SMEM_BYTES (3 * STG_SZ * 2)     // 92160

__global__ __launch_bounds__(256, 1)
void gemm_h(int M, int N, int K,
            const __half* __restrict__ A, int lda,
            const __half* __restrict__ Bt, int ldb,
            void* __restrict__ C, int ldc,
            float scale, int mode)
{
    extern __shared__ __half gsm[];
    const int tid = threadIdx.x, lane = tid & 31, wid = tid >> 5;
    const int gid = lane >> 2, t4 = lane & 3;
    const int wm = wid >> 1, wn = wid & 1;
    const int bm = blockIdx.y * GBM, bn = blockIdx.x * GBN;
    const uint32_t sbase = (uint32_t)__cvta_generic_to_shared(gsm);

    const int ar = tid >> 2;
    const int ac = (tid & 3) * 8;        // half index of 16B chunk

    auto load_stage = [&](int kt, int stg) {
        const __half* Ag = A + (size_t)bm * lda + kt * GBK;
        uint32_t as = sbase + stg * STG_SZ * 2;
#pragma unroll
        for (int i = 0; i < 4; i++) {
            int r = ar + 64 * i;
            cp16(as + (r * ALD + ac) * 2, Ag + (size_t)r * lda + ac);
        }
        const __half* Bg = Bt + (size_t)bn * ldb + kt * GBK;
        uint32_t bs = sbase + (stg * STG_SZ + STG_A) * 2;
#pragma unroll
        for (int i = 0; i < 2; i++) {
            int r = ar + 64 * i;
            cp16(bs + (r * BLD + ac) * 2, Bg + (size_t)r * ldb + ac);
        }
        cp_commit();
    };

    float acc[4][8][4];
#pragma unroll
    for (int mi = 0; mi < 4; mi++)
#pragma unroll
        for (int ni = 0; ni < 8; ni++)
#pragma unroll
            for (int x = 0; x < 4; x++) acc[mi][ni][x] = 0.f;

    const int nk = K / GBK;
    load_stage(0, 0);
    load_stage(1, 1);

    const int arow = (lane & 7) + 8 * ((lane >> 3) & 1);
    const int acol = 8 * (lane >> 4);
    const int brow = lane & 7;
    const int bcol = 8 * (lane >> 3);

    for (int kt = 0; kt < nk; kt++) {
        cp_wait1();
        __syncthreads();
        if (kt + 2 < nk) load_stage(kt + 2, (kt + 2) % 3);
        else cp_commit();

        const int stg = kt % 3;
        const uint32_t as = sbase + stg * STG_SZ * 2;
        const uint32_t bs = sbase + (stg * STG_SZ + STG_A) * 2;

        uint32_t bf[8][4];
#pragma unroll
        for (int ni = 0; ni < 8; ni++) {
            int n0 = wn * 64 + ni * 8;
            ldsm_x4(bf[ni][0], bf[ni][1], bf[ni][2], bf[ni][3],
                    bs + ((n0 + brow) * BLD + bcol) * 2);
        }
#pragma unroll
        for (int ks = 0; ks < 2; ks++) {
            uint32_t af[4][4];
#pragma unroll
            for (int mi = 0; mi < 4; mi++) {
                int m0 = wm * 64 + mi * 16;
                ldsm_x4(af[mi][0], af[mi][1], af[mi][2], af[mi][3],
                        as + ((m0 + arow) * ALD + ks * 16 + acol) * 2);
            }
#pragma unroll
            for (int ni = 0; ni < 8; ni++)
#pragma unroll
                for (int mi = 0; mi < 4; mi++)
                    mma_h(acc[mi][ni], af[mi], bf[ni][ks * 2], bf[ni][ks * 2 + 1]);
        }
    }

    // epilogue
#pragma unroll
    for (int mi = 0; mi < 4; mi++) {
        int row = bm + wm * 64 + mi * 16 + gid;
#pragma unroll
        for (int ni = 0; ni < 8; ni++) {
            int col = bn + wn * 64 + ni * 8 + 2 * t4;
            float v0 = acc[mi][ni][0] * scale;
            float v1 = acc[mi][ni][1] * scale;
            float v2 = acc[mi][ni][2] * scale;
            float v3 = acc[mi][ni][3] * scale;
            if (mode == 0) {
                float* Cf = (float*)C;
                *(float2*)(Cf + (size_t)row * ldc + col)       = make_float2(v0, v1);
                *(float2*)(Cf + (size_t)(row + 8) * ldc + col) = make_float2(v2, v3);
            } else if (mode == 1) {
                __half* Ch = (__half*)C;
                *(__half2*)(Ch + (size_t)row * ldc + col)       = __floats2half2_rn(v0, v1);
                *(__half2*)(Ch + (size_t)(row + 8) * ldc + col) = __floats2half2_rn(v2, v3);
            } else {
                __half* Ch = (__half*)C;      // [N][M], ldc = M
                Ch[(size_t)col * ldc + row]           = __float2half_rn(v0);
                Ch[(size_t)(col + 1) * ldc + row]     = __float2half_rn(v1);
                Ch[(size_t)col * ldc + row + 8]       = __float2half_rn(v2);
                Ch[(size_t)(col + 1) * ldc + row + 8] = __float2half_rn(v3);
            }
        }
    }
}

// =======================================================================
// fp16 flash attention. Br=128 (8 warps x 16 rows), Bc=64, D=128.
// Q frags in registers; V consumed pre-transposed; zero shuffles in PV.
// 3-stage cp.async K/V pipeline. Scores already scaled by 1/sqrt(d)*log2e.
// =======================================================================
#define QLDH 136
#define KLDH 136
#define VLDH 72
#define Q_SZ   (128 * QLDH)               // 17408
#define K_STG  (64 * KLDH)                // 8704
#define V_STG  (128 * VLDH)               // 9216
#define K_OFF  Q_SZ
#define V_OFF  (Q_SZ + 3 * K_STG)
#define FA_SMEM_BYTES ((Q_SZ + 3 * K_STG + 3 * V_STG) * 2)   // 142336

__global__ __launch_bounds__(256, 1)
void flash_attn_h(const __half* __restrict__ Qg,
                  const __half* __restrict__ Kg,
                  const __half* __restrict__ Vtg,   // [2048][4096]
                  __half* __restrict__ Og)
{
    extern __shared__ __half fsm[];
    const uint32_t sb = (uint32_t)__cvta_generic_to_shared(fsm);

    const int qt   = (gridDim.x - 1) - blockIdx.x;
    const int bh   = blockIdx.y;
    const int b    = bh >> 4;
    const int h    = bh & 15;
    const int tid  = threadIdx.x;
    const int lane = tid & 31;
    const int wid  = tid >> 5;
    const int gid  = lane >> 2;
    const int t4   = lane & 3;

    // ---- Q tile -> smem (cp.async, group 0) ----
    {
        const __half* qb = Qg + (size_t)(b * S_LEN + qt * 128) * HIDDEN + h * HD;
#pragma unroll
        for (int i = 0; i < 8; i++) {
            int g = tid + 256 * i;
            int r = g >> 4, c = (g & 15) * 8;
            cp16(sb + (r * QLDH + c) * 2, qb + (size_t)r * HIDDEN + c);
        }
        cp_commit();
    }

    auto load_kv = [&](int kt, int stg) {
        const __half* kb = Kg + (size_t)(b * S_LEN + kt * 64) * HIDDEN + h * HD;
        uint32_t ks = sb + (K_OFF + stg * K_STG) * 2;
#pragma unroll
        for (int i = 0; i < 4; i++) {
            int g = tid + 256 * i;
            int r = g >> 4, c = (g & 15) * 8;
            cp16(ks + (r * KLDH + c) * 2, kb + (size_t)r * HIDDEN + c);
        }
        const __half* vb = Vtg + (size_t)(h * HD) * ROWS + b * S_LEN + kt * 64;
        uint32_t vs = sb + (V_OFF + stg * V_STG) * 2;
#pragma unroll
        for (int i = 0; i < 4; i++) {
            int g = tid + 256 * i;
            int r = g >> 3, c = (g & 7) * 8;
            cp16(vs + (r * VLDH + c) * 2, vb + (size_t)r * ROWS + c);
        }
        cp_commit();
    };

    const int nkt = 2 * qt + 2;
    load_kv(0, 0);
    if (nkt > 1) load_kv(1, 1); else cp_commit();

    const int arow = (lane & 7) + 8 * ((lane >> 3) & 1);
    const int acol = 8 * (lane >> 4);
    const int brow = lane & 7;
    const int bcol = 8 * (lane >> 3);
    const int r0 = wid * 16;

    uint32_t q[8][4];                  // Q fragments (loaded at kt==0)
    float o[16][4];
#pragma unroll
    for (int ni = 0; ni < 16; ni++)
#pragma unroll
        for (int x = 0; x < 4; x++) o[ni][x] = 0.f;
    float m_lo = -1e30f, m_hi = -1e30f, l_lo = 0.f, l_hi = 0.f;

    const int row_lo = qt * 128 + r0 + gid;
    const int row_hi = row_lo + 8;

    for (int kt = 0; kt < nkt; kt++) {
        cp_wait1();
        __syncthreads();
        if (kt + 2 < nkt) load_kv(kt + 2, (kt + 2) % 3);
        else cp_commit();

        if (kt == 0) {
#pragma unroll
            for (int ks = 0; ks < 8; ks++)
                ldsm_x4(q[ks][0], q[ks][1], q[ks][2], q[ks][3],
                        sb + ((r0 + arow) * QLDH + ks * 16 + acol) * 2);
        }

        const int stg = kt % 3;
        const uint32_t ksb = sb + (K_OFF + stg * K_STG) * 2;
        const uint32_t vsb = sb + (V_OFF + stg * V_STG) * 2;

        // ---- S = Q @ K^T ----
        float s[8][4];
#pragma unroll
        for (int ni = 0; ni < 8; ni++)
#pragma unroll
            for (int x = 0; x < 4; x++) s[ni][x] = 0.f;

#pragma unroll
        for (int kc = 0; kc < 4; kc++) {
#pragma unroll
            for (int ni = 0; ni < 8; ni++) {
                uint32_t kb4[4];
                ldsm_x4(kb4[0], kb4[1], kb4[2], kb4[3],
                        ksb + ((ni * 8 + brow) * KLDH + kc * 32 + bcol) * 2);
                mma_h(s[ni], q[kc * 2],     kb4[0], kb4[1]);
                mma_h(s[ni], q[kc * 2 + 1], kb4[2], kb4[3]);
            }
        }

        // ---- causal mask ----
        if (kt >= 2 * qt) {
            const int cb = kt * 64 + 2 * t4;
#pragma unroll
            for (int ni = 0; ni < 8; ni++) {
                int c0 = cb + ni * 8;
                if (c0     > row_lo) s[ni][0] = -1e30f;
                if (c0 + 1 > row_lo) s[ni][1] = -1e30f;
                if (c0     > row_hi) s[ni][2] = -1e30f;
                if (c0 + 1 > row_hi) s[ni][3] = -1e30f;
            }
        }

        // ---- online softmax (base-2, quad reduce) ----
        float mlo = -1e30f, mhi = -1e30f;
#pragma unroll
        for (int ni = 0; ni < 8; ni++) {
            mlo = fmaxf(mlo, fmaxf(s[ni][0], s[ni][1]));
            mhi = fmaxf(mhi, fmaxf(s[ni][2], s[ni][3]));
        }
        mlo = fmaxf(mlo, __shfl_xor_sync(0xffffffffu, mlo, 1));
        mlo = fmaxf(mlo, __shfl_xor_sync(0xffffffffu, mlo, 2));
        mhi = fmaxf(mhi, __shfl_xor_sync(0xffffffffu, mhi, 1));
        mhi = fmaxf(mhi, __shfl_xor_sync(0xffffffffu, mhi, 2));

        float mnl = fmaxf(m_lo, mlo), mnh = fmaxf(m_hi, mhi);
        float clo = exp2f(m_lo - mnl), chi = exp2f(m_hi - mnh);
        m_lo = mnl; m_hi = mnh;

        float rlo = 0.f, rhi = 0.f;
#pragma unroll
        for (int ni = 0; ni < 8; ni++) {
            s[ni][0] = exp2f(s[ni][0] - mnl);
            s[ni][1] = exp2f(s[ni][1] - mnl);
            s[ni][2] = exp2f(s[ni][2] - mnh);
            s[ni][3] = exp2f(s[ni][3] - mnh);
            rlo += s[ni][0] + s[ni][1];
            rhi += s[ni][2] + s[ni][3];
        }
        rlo += __shfl_xor_sync(0xffffffffu, rlo, 1);
        rlo += __shfl_xor_sync(0xffffffffu, rlo, 2);
        rhi += __shfl_xor_sync(0xffffffffu, rhi, 1);
        rhi += __shfl_xor_sync(0xffffffffu, rhi, 2);
        l_lo = l_lo * clo + rlo;
        l_hi = l_hi * chi + rhi;

#pragma unroll
        for (int ni = 0; ni < 16; ni++) {
            o[ni][0] *= clo; o[ni][1] *= clo;
            o[ni][2] *= chi; o[ni][3] *= chi;
        }

        // ---- P fragments: direct pack, no shuffles ----
        uint32_t pa[4][4];
#pragma unroll
        for (int kc = 0; kc < 4; kc++) {
            pa[kc][0] = h2pack(s[2 * kc][1],     s[2 * kc][0]);
            pa[kc][1] = h2pack(s[2 * kc][3],     s[2 * kc][2]);
            pa[kc][2] = h2pack(s[2 * kc + 1][1], s[2 * kc + 1][0]);
            pa[kc][3] = h2pack(s[2 * kc + 1][3], s[2 * kc + 1][2]);
        }

        // ---- O += P @ V ----
#pragma unroll
        for (int vc = 0; vc < 2; vc++) {
#pragma unroll
            for (int ni = 0; ni < 16; ni++) {
                uint32_t vb4[4];
                ldsm_x4(vb4[0], vb4[1], vb4[2], vb4[3],
                        vsb + ((ni * 8 + brow) * VLDH + vc * 32 + bcol) * 2);
                mma_h(o[ni], pa[vc * 2],     vb4[0], vb4[1]);
                mma_h(o[ni], pa[vc * 2 + 1], vb4[2], vb4[3]);
            }
        }
    }

    // ---- normalize + write fp16 ----
    const float il0 = 1.f / l_lo, il1 = 1.f / l_hi;
    __half* olo = Og + (size_t)(b * S_LEN + row_lo) * HIDDEN + h * HD;
    __half* ohi = Og + (size_t)(b * S_LEN + row_hi) * HIDDEN + h * HD;
#pragma unroll
    for (int ni = 0; ni < 16; ni++) {
        int col = ni * 8 + 2 * t4;
        *(__half2*)(olo + col) = __floats2half2_rn(o[ni][0] * il0, o[ni][1] * il0);
        *(__half2*)(ohi + col) = __floats2half2_rn(o[ni][2] * il1, o[ni][3] * il1);
    }
}

// ---------------- launch ----------------
extern "C" void kernel_launch(void* const* d_in, const int* in_sizes, int n_in,
                              void* d_out, int out_size)
{
    const float* h       = (const float*)d_in[0];
    const float* Wq      = (const float*)d_in[3];
    const float* Wkv     = (const float*)d_in[4];
    const float* Wk_up   = (const float*)d_in[5];
    const float* Wv_up   = (const float*)d_in[6];
    const float* Wq_rope = (const float*)d_in[7];
    const float* Wk_rope = (const float*)d_in[8];
    const float* Wo      = (const float*)d_in[9];
    float* out = (float*)d_out;

    __half *ph16, *pWqT, *pWkvT, *pWkT, *pWvT, *pWoT, *pq, *pkv, *pk, *pvt, *pao;
    cudaGetSymbolAddress((void**)&ph16,  g_h16);
    cudaGetSymbolAddress((void**)&pWqT,  g_WqT);
    cudaGetSymbolAddress((void**)&pWkvT, g_WkvT);
    cudaGetSymbolAddress((void**)&pWkT,  g_WkT);
    cudaGetSymbolAddress((void**)&pWvT,  g_WvT);
    cudaGetSymbolAddress((void**)&pWoT,  g_WoT);
    cudaGetSymbolAddress((void**)&pq,    g_q16);
    cudaGetSymbolAddress((void**)&pkv,   g_kv16);
    cudaGetSymbolAddress((void**)&pk,    g_k16);
    cudaGetSymbolAddress((void**)&pvt,   g_vt16);
    cudaGetSymbolAddress((void**)&pao,   g_ao16);

    static int attr_done = 0;
    if (!attr_done) {
        cudaFuncSetAttribute(gemm_h,
            cudaFuncAttributeMaxDynamicSharedMemorySize, G_SMEM_BYTES);
        cudaFuncSetAttribute(flash_attn_h,
            cudaFuncAttributeMaxDynamicSharedMemorySize, FA_SMEM_BYTES);
        attr_done = 1;
    }

    // ---- pre-pass: convert + fold + transpose weights ----
    {
        int n = ROWS * HIDDEN;
        cvt_f2h<<<n / 4 / 256, 256>>>(h, ph16, n);
        dim3 tb(32, 8);
        transpose_cvt<<<dim3(HIDDEN / 32, HIDDEN / 32), tb>>>(Wq, Wq_rope, pWqT, HIDDEN, HIDDEN);
        transpose_cvt<<<dim3((2 * LATENT) / 32, HIDDEN / 32), tb>>>(Wkv, nullptr, pWkvT, HIDDEN, 2 * LATENT);
        transpose_cvt<<<dim3(HIDDEN / 32, LATENT / 32), tb>>>(Wk_up, Wk_rope, pWkT, LATENT, HIDDEN);
        transpose_cvt<<<dim3(HIDDEN / 32, LATENT / 32), tb>>>(Wv_up, nullptr, pWvT, LATENT, HIDDEN);
        transpose_cvt<<<dim3(HIDDEN / 32, HIDDEN / 32), tb>>>(Wo, nullptr, pWoT, HIDDEN, HIDDEN);
    }

    dim3 blk(256);
    // q = fp16(h @ Wq_eff * qk_scale)
    gemm_h<<<dim3(HIDDEN / GBN, ROWS / GBM), blk, G_SMEM_BYTES>>>(
        ROWS, HIDDEN, HIDDEN, ph16, HIDDEN, pWqT, HIDDEN, pq, HIDDEN, QK_SCALE, 1);
    // kv = fp16(h @ Wkv)
    gemm_h<<<dim3((2 * LATENT) / GBN, ROWS / GBM), blk, G_SMEM_BYTES>>>(
        ROWS, 2 * LATENT, HIDDEN, ph16, HIDDEN, pWkvT, HIDDEN, pkv, 2 * LATENT, 1.f, 1);
    // k = fp16(kv_k @ Wk_eff)
    gemm_h<<<dim3(HIDDEN / GBN, ROWS / GBM), blk, G_SMEM_BYTES>>>(
        ROWS, HIDDEN, LATENT, pkv, 2 * LATENT, pWkT, LATENT, pk, HIDDEN, 1.f, 1);
    // v^T = fp16((kv_v @ Wv_up)^T)  -> [2048][4096]
    gemm_h<<<dim3(HIDDEN / GBN, ROWS / GBM), blk, G_SMEM_BYTES>>>(
        ROWS, HIDDEN, LATENT, pkv + LATENT, 2 * LATENT, pWvT, LATENT, pvt, ROWS, 1.f, 2);

    // attention
    flash_attn_h<<<dim3(S_LEN / 128, BATCH * NHEADS), blk, FA_SMEM_BYTES>>>(
        pq, pk, pvt, pao);

    // out = fp32(ao @ Wo)
    gemm_h<<<dim3(HIDDEN / GBN, ROWS / GBM), blk, G_SMEM_BYTES>>>(
        ROWS, HIDDEN, HIDDEN, pao, HIDDEN, pWoT, HIDDEN, out, HIDDEN, 1.f, 0);
}